// round 3
// baseline (speedup 1.0000x reference)
#include <cuda_runtime.h>

// CGMMTransition: N=10000, L=5, A=6, C=20, C2=20
// Outputs (concatenated in d_out, fp32):
//   p_Q_given_obs        [N, C]           at offset 0
//   transition_posterior [N, L, A, C, C2] at offset N*C
//   rightmost_term       [N, L, A, C, C2] at offset N*C + N*L*A*C*C2

#define LVAL   5
#define AVAL   6
#define CVAL   20
#define C2VAL  20
#define LA     30      // L*A
#define KDIM   600     // LA*C2
#define PER_N  12000   // LA*C*C2
#define NTHREADS 256

// Pre-transposed T for the p_Q matvec: M[k][c] = T[la, c, j], k = la*20 + j.
// __device__ scratch (no allocation in kernel_launch).
__device__ float g_M[KDIM * CVAL];

__global__ void reorder_T_kernel(const float* __restrict__ T)
{
    int m = blockIdx.x * blockDim.x + threadIdx.x;   // index into M
    if (m >= KDIM * CVAL) return;
    int k  = m / CVAL;
    int c  = m % CVAL;
    int la = k / C2VAL;
    int j  = k % C2VAL;
    g_M[m] = T[la * (CVAL * C2VAL) + c * C2VAL + j];
}

__global__ void __launch_bounds__(NTHREADS)
cgmm_kernel(const float* __restrict__ stats,
            const float* __restrict__ layerS,
            const float* __restrict__ arcS,
            float* __restrict__ out_pq,
            float* __restrict__ out_tp,
            float* __restrict__ out_rt,
            const float* __restrict__ T)
{
    __shared__ float s_stats[KDIM];
    __shared__ float s_ws[KDIM];    // stats * inv * w  (matvec input)
    __shared__ float s_inv[LA];
    __shared__ float s_w[LA];

    const int n    = blockIdx.x;
    const int tid  = threadIdx.x;
    const int warp = tid >> 5;
    const int lane = tid & 31;

    // ---- Phase 0: stage stats[n] (600 floats = 150 float4) into shared ----
    const float4* g_stats4 =
        reinterpret_cast<const float4*>(stats + (size_t)n * KDIM);
    if (tid < KDIM / 4) {
        float4 v = __ldcs(&g_stats4[tid]);   // streamed: read exactly once
        reinterpret_cast<float4*>(s_stats)[tid] = v;
    }
    __syncthreads();

    // ---- Phase 1: per-(l,a) inverse row-sum and weight ----
    if (tid < LA) {
        float s = 0.0f;
        #pragma unroll
        for (int j = 0; j < C2VAL; ++j) s += s_stats[tid * C2VAL + j];
        s_inv[tid] = (s == 0.0f) ? 1.0f : 1.0f / s;
        s_w[tid]   = layerS[tid / AVAL] * arcS[tid];
    }
    __syncthreads();

    // ---- Phase 1.5: weighted stats vector for the p_Q matvec ----
    // (KDIM=600 > blockDim: MUST stride — this was the R2 bug)
    for (int k = tid; k < KDIM; k += NTHREADS) {
        const int la = k / C2VAL;
        s_ws[k] = s_stats[k] * s_inv[la] * s_w[la];
    }
    __syncthreads();

    if (warp == 0) {
        // ---- p_Q matvec: p_Q[c] = sum_k s_ws[k] * M[k][c] ----
        // lanes 0..19 each own one c; M rows are 80B contiguous -> coalesced.
        if (lane < CVAL) {
            float acc0 = 0.0f, acc1 = 0.0f;
            #pragma unroll 4
            for (int k = 0; k < KDIM; k += 2) {
                acc0 = fmaf(__ldg(&g_M[(k    ) * CVAL + lane]), s_ws[k    ], acc0);
                acc1 = fmaf(__ldg(&g_M[(k + 1) * CVAL + lane]), s_ws[k + 1], acc1);
            }
            out_pq[(size_t)n * CVAL + lane] = acc0 + acc1;
        }
    } else {
        // ---- main elementwise stream (warps 1..7, 224 threads) ----
        // rt = T * stats * inv ; tp = rt * w. Coalesced float4 streaming stores.
        const size_t base = (size_t)n * PER_N;   // 48000 B -> 16B aligned
        const float4* T4  = reinterpret_cast<const float4*>(T);
        float4* rt4 = reinterpret_cast<float4*>(out_rt + base);
        float4* tp4 = reinterpret_cast<float4*>(out_tp + base);

        for (int i = tid - 32; i < PER_N / 4; i += NTHREADS - 32) {
            const int e   = i * 4;
            const int la  = e / (CVAL * C2VAL);
            const int c2b = e % C2VAL;           // in {0,4,8,12,16}: no straddle
            const float4 t  = __ldg(&T4[i]);     // L1-resident, coalesced
            const float4 sv = *reinterpret_cast<const float4*>(
                                  s_stats + la * C2VAL + c2b);
            const float inv = s_inv[la];
            const float w   = s_w[la];
            float4 r, p;
            r.x = t.x * sv.x * inv;  r.y = t.y * sv.y * inv;
            r.z = t.z * sv.z * inv;  r.w = t.w * sv.w * inv;
            p.x = r.x * w;  p.y = r.y * w;  p.z = r.z * w;  p.w = r.w * w;
            __stcs(&rt4[i], r);   // streaming stores: don't pollute L2
            __stcs(&tp4[i], p);
        }
    }
}

extern "C" void kernel_launch(void* const* d_in, const int* in_sizes, int n_in,
                              void* d_out, int out_size)
{
    const float* stats  = (const float*)d_in[0];  // [N, L, A, C2]
    const float* layerS = (const float*)d_in[1];  // [L]
    const float* arcS   = (const float*)d_in[2];  // [L, A]
    const float* T      = (const float*)d_in[3];  // [L, A, C, C2]

    const int N = in_sizes[0] / KDIM;

    float* out    = (float*)d_out;
    float* out_pq = out;
    float* out_tp = out_pq + (size_t)N * CVAL;
    float* out_rt = out_tp + (size_t)N * PER_N;

    reorder_T_kernel<<<(KDIM * CVAL + 255) / 256, 256>>>(T);
    cgmm_kernel<<<N, NTHREADS>>>(stats, layerS, arcS,
                                 out_pq, out_tp, out_rt, T);
}

// round 4
// speedup vs baseline: 1.0657x; 1.0657x over previous
#include <cuda_runtime.h>

// CGMMTransition: N=10000, L=5, A=6, C=20, C2=20
// Outputs (concatenated in d_out, fp32):
//   p_Q_given_obs        [N, C]           at offset 0
//   transition_posterior [N, L, A, C, C2] at offset N*C
//   rightmost_term       [N, L, A, C, C2] at offset N*C + N*L*A*C*C2
//
// Key identity: p_Q[n,c] = sum over (la,c2) of transition_posterior[n,la,c,c2],
// so p_Q falls out of the main streaming loop via shared-memory accumulation.

#define LVAL   5
#define AVAL   6
#define CVAL   20
#define C2VAL  20
#define LA     30      // L*A
#define KDIM   600     // LA*C2
#define PER_N  12000   // LA*C*C2
#define NTHREADS 256

__global__ void __launch_bounds__(NTHREADS)
cgmm_kernel(const float* __restrict__ stats,
            const float* __restrict__ layerS,
            const float* __restrict__ arcS,
            const float* __restrict__ T,
            float* __restrict__ out_pq,
            float* __restrict__ out_tp,
            float* __restrict__ out_rt)
{
    __shared__ float s_stats[KDIM];
    __shared__ float s_inv[LA];
    __shared__ float s_w[LA];
    __shared__ float s_pq[CVAL];

    const int n   = blockIdx.x;
    const int tid = threadIdx.x;

    // ---- Phase 0: stage stats[n] (600 floats = 150 float4) into shared ----
    const float4* g_stats4 =
        reinterpret_cast<const float4*>(stats + (size_t)n * KDIM);
    if (tid < KDIM / 4) {
        float4 v = __ldcs(&g_stats4[tid]);   // streamed: each element read once
        reinterpret_cast<float4*>(s_stats)[tid] = v;
    }
    if (tid < CVAL) s_pq[tid] = 0.0f;
    __syncthreads();

    // ---- Phase 1: per-(l,a) inverse row-sum and weight ----
    if (tid < LA) {
        float s = 0.0f;
        #pragma unroll
        for (int j = 0; j < C2VAL; ++j) s += s_stats[tid * C2VAL + j];
        s_inv[tid] = (s == 0.0f) ? 1.0f : 1.0f / s;
        s_w[tid]   = layerS[tid / AVAL] * arcS[tid];
    }
    __syncthreads();

    // ---- Phase 2: main elementwise stream, ALL 8 warps ----
    // rt = T * stats * inv ; tp = rt * w ; p_Q[c] += sum4(tp) (shared atomic).
    const size_t base = (size_t)n * PER_N;   // 48000 B per n -> 16B aligned
    const float4* T4  = reinterpret_cast<const float4*>(T);
    float4* rt4 = reinterpret_cast<float4*>(out_rt + base);
    float4* tp4 = reinterpret_cast<float4*>(out_tp + base);

    for (int i = tid; i < PER_N / 4; i += NTHREADS) {
        const int e   = i * 4;
        const int la  = e / (CVAL * C2VAL);
        const int c   = (e / C2VAL) % CVAL;
        const int c2b = e % C2VAL;            // in {0,4,8,12,16}: no straddle
        const float4 t  = __ldg(&T4[i]);      // L1-resident, coalesced
        const float4 sv = *reinterpret_cast<const float4*>(
                              s_stats + la * C2VAL + c2b);
        const float inv = s_inv[la];
        const float w   = s_w[la];
        float4 r, p;
        r.x = t.x * sv.x * inv;  r.y = t.y * sv.y * inv;
        r.z = t.z * sv.z * inv;  r.w = t.w * sv.w * inv;
        p.x = r.x * w;  p.y = r.y * w;  p.z = r.z * w;  p.w = r.w * w;
        __stcs(&rt4[i], r);    // streaming stores: don't pollute L2
        __stcs(&tp4[i], p);
        atomicAdd(&s_pq[c], (p.x + p.y) + (p.z + p.w));
    }

    __syncthreads();
    if (tid < CVAL) out_pq[(size_t)n * CVAL + tid] = s_pq[tid];
}

extern "C" void kernel_launch(void* const* d_in, const int* in_sizes, int n_in,
                              void* d_out, int out_size)
{
    const float* stats  = (const float*)d_in[0];  // [N, L, A, C2]
    const float* layerS = (const float*)d_in[1];  // [L]
    const float* arcS   = (const float*)d_in[2];  // [L, A]
    const float* T      = (const float*)d_in[3];  // [L, A, C, C2]

    const int N = in_sizes[0] / KDIM;

    float* out    = (float*)d_out;
    float* out_pq = out;
    float* out_tp = out_pq + (size_t)N * CVAL;
    float* out_rt = out_tp + (size_t)N * PER_N;

    cgmm_kernel<<<N, NTHREADS>>>(stats, layerS, arcS, T,
                                 out_pq, out_tp, out_rt);
}

// round 5
// speedup vs baseline: 1.3546x; 1.2711x over previous
#include <cuda_runtime.h>

// CGMMTransition: N=10000, L=5, A=6, C=20, C2=20
// Outputs (concatenated in d_out, fp32):
//   p_Q_given_obs        [N, C]           at offset 0
//   transition_posterior [N, L, A, C, C2] at offset N*C
//   rightmost_term       [N, L, A, C, C2] at offset N*C + N*L*A*C*C2
//
// p_Q[n,c] = sum_{la,c2} transition_posterior[n,la,c,c2]: accumulated from the
// main stream via warp-segmented shuffle reduction (c is constant over runs of
// 5 float4s), so only segment-head lanes touch shared atomics (<=8 per
// warp-iter, distinct addresses) instead of 32 conflicting ATOMS.

#define LVAL   5
#define AVAL   6
#define CVAL   20
#define C2VAL  20
#define LA     30      // L*A
#define KDIM   600     // LA*C2
#define PER_N  12000   // LA*C*C2
#define PER_N4 3000    // PER_N/4
#define NTHREADS 256
#define NITER  ((PER_N4 + NTHREADS - 1) / NTHREADS)   // 12

__global__ void __launch_bounds__(NTHREADS)
cgmm_kernel(const float* __restrict__ stats,
            const float* __restrict__ layerS,
            const float* __restrict__ arcS,
            const float* __restrict__ T,
            float* __restrict__ out_pq,
            float* __restrict__ out_tp,
            float* __restrict__ out_rt)
{
    __shared__ float s_stats[KDIM];
    __shared__ float s_inv[LA];
    __shared__ float s_w[LA];
    __shared__ float s_pq[CVAL];

    const int n    = blockIdx.x;
    const int tid  = threadIdx.x;
    const int lane = tid & 31;

    // ---- Phase 0: stage stats[n] (600 floats = 150 float4) into shared ----
    const float4* g_stats4 =
        reinterpret_cast<const float4*>(stats + (size_t)n * KDIM);
    if (tid < KDIM / 4) {
        float4 v = __ldcs(&g_stats4[tid]);   // streamed: each element read once
        reinterpret_cast<float4*>(s_stats)[tid] = v;
    }
    if (tid < CVAL) s_pq[tid] = 0.0f;
    __syncthreads();

    // ---- Phase 1: per-(l,a) inverse row-sum and weight ----
    if (tid < LA) {
        float s = 0.0f;
        #pragma unroll
        for (int j = 0; j < C2VAL; ++j) s += s_stats[tid * C2VAL + j];
        s_inv[tid] = (s == 0.0f) ? 1.0f : 1.0f / s;
        s_w[tid]   = layerS[tid / AVAL] * arcS[tid];
    }
    __syncthreads();

    // ---- Phase 2: main elementwise stream, all warps ----
    const size_t base = (size_t)n * PER_N;   // 48000 B per n -> 16B aligned
    const float4* T4  = reinterpret_cast<const float4*>(T);
    float4* rt4 = reinterpret_cast<float4*>(out_rt + base);
    float4* tp4 = reinterpret_cast<float4*>(out_tp + base);

    // Incremental index state: i = tid + 256*k.
    // m = i % 5  (256 == 1 mod 5 -> m advances by 1 each iter)
    // c = (i/5) % 20  (i/5 advances by 51 or 52 -> c += 11 or 12 mod 20)
    int m = tid % 5;
    int c = (tid / 5) % CVAL;

    #pragma unroll
    for (int k = 0; k < NITER; ++k) {
        const int  i      = tid + k * NTHREADS;
        const bool active = (i < PER_N4);

        float v = 0.0f;
        if (active) {
            const int e   = i * 4;
            const int la  = e / (CVAL * C2VAL);
            const int c2b = e % C2VAL;          // in {0,4,8,12,16}: no straddle
            const float4 t  = __ldg(&T4[i]);    // L1-resident, coalesced
            const float4 sv = *reinterpret_cast<const float4*>(
                                  s_stats + la * C2VAL + c2b);
            const float inv = s_inv[la];
            const float w   = s_w[la];
            float4 r, p;
            r.x = t.x * sv.x * inv;  r.y = t.y * sv.y * inv;
            r.z = t.z * sv.z * inv;  r.w = t.w * sv.w * inv;
            p.x = r.x * w;  p.y = r.y * w;  p.z = r.z * w;  p.w = r.w * w;
            __stcs(&rt4[i], r);   // streaming stores: don't pollute L2
            __stcs(&tp4[i], p);
            v = (p.x + p.y) + (p.z + p.w);
        }

        // Segmented reduction: segments = runs of 5 consecutive i with equal c.
        // After steps d=1,2,4 (cond m+d<=4), head lanes hold their segment's
        // in-warp partial sum. Inactive lanes contribute v=0; shuffles are
        // executed by all 32 lanes (no divergence on the sync mask).
        float o;
        o = __shfl_down_sync(0xFFFFFFFFu, v, 1);
        if (m <= 3 && lane < 31) v += o;
        o = __shfl_down_sync(0xFFFFFFFFu, v, 2);
        if (m <= 2 && lane < 30) v += o;
        o = __shfl_down_sync(0xFFFFFFFFu, v, 4);
        if (m == 0 && lane < 28) v += o;

        if (active && (m == 0 || lane == 0))
            atomicAdd(&s_pq[c], v);            // <=8 lanes, distinct addresses

        // advance m, c for next iteration
        const bool wrap = (m == 4);
        m = wrap ? 0 : m + 1;
        c += wrap ? 12 : 11;
        if (c >= CVAL) c -= CVAL;
    }

    __syncthreads();
    if (tid < CVAL) out_pq[(size_t)n * CVAL + tid] = s_pq[tid];
}

extern "C" void kernel_launch(void* const* d_in, const int* in_sizes, int n_in,
                              void* d_out, int out_size)
{
    const float* stats  = (const float*)d_in[0];  // [N, L, A, C2]
    const float* layerS = (const float*)d_in[1];  // [L]
    const float* arcS   = (const float*)d_in[2];  // [L, A]
    const float* T      = (const float*)d_in[3];  // [L, A, C, C2]

    const int N = in_sizes[0] / KDIM;

    float* out    = (float*)d_out;
    float* out_pq = out;
    float* out_tp = out_pq + (size_t)N * CVAL;
    float* out_rt = out_tp + (size_t)N * PER_N;

    cgmm_kernel<<<N, NTHREADS>>>(stats, layerS, arcS, T,
                                 out_pq, out_tp, out_rt);
}

// round 6
// speedup vs baseline: 1.3645x; 1.0073x over previous
#include <cuda_runtime.h>

// CGMMTransition: N=10000, L=5, A=6, C=20, C2=20
// Outputs (concatenated in d_out, fp32):
//   p_Q_given_obs        [N, C]           at offset 0
//   transition_posterior [N, L, A, C, C2] at offset N*C
//   rightmost_term       [N, L, A, C, C2] at offset N*C + N*L*A*C*C2
//
// p_Q[n,c] = sum_{la,c2} transition_posterior[n,la,c,c2]: accumulated from the
// main stream. Warp-segmented shuffle reduction (c constant over runs of 5
// float4s) leaves partials on head lanes; head lanes have DISTINCT c within a
// warp-iteration, so per-warp shared bins can be updated with plain
// (non-atomic) read-modify-write — zero ATOMS in the kernel.

#define LVAL   5
#define AVAL   6
#define CVAL   20
#define C2VAL  20
#define LA     30      // L*A
#define KDIM   600     // LA*C2
#define PER_N  12000   // LA*C*C2
#define PER_N4 3000    // PER_N/4
#define NTHREADS 256
#define NWARPS 8
#define NITER  12      // ceil(3000/256); iter 11 partial (tid < 184)
#define TAIL   (PER_N4 - 11 * NTHREADS)   // 184

__global__ void __launch_bounds__(NTHREADS, 8)
cgmm_kernel(const float* __restrict__ stats,
            const float* __restrict__ layerS,
            const float* __restrict__ arcS,
            const float* __restrict__ T,
            float* __restrict__ out_pq,
            float* __restrict__ out_tp,
            float* __restrict__ out_rt)
{
    __shared__ float s_stats[KDIM];
    __shared__ float s_inv[LA];
    __shared__ float s_w[LA];
    __shared__ float s_pqw[NWARPS][CVAL];   // per-warp c-bins (non-atomic)

    const int n    = blockIdx.x;
    const int tid  = threadIdx.x;
    const int warp = tid >> 5;
    const int lane = tid & 31;

    // ---- Phase 0: stage stats[n] (600 floats = 150 float4) into shared ----
    const float4* g_stats4 =
        reinterpret_cast<const float4*>(stats + (size_t)n * KDIM);
    if (tid < KDIM / 4) {
        float4 v = __ldcs(&g_stats4[tid]);   // streamed: each element read once
        reinterpret_cast<float4*>(s_stats)[tid] = v;
    }
    if (tid < NWARPS * CVAL)
        reinterpret_cast<float*>(s_pqw)[tid] = 0.0f;
    __syncthreads();

    // ---- Phase 1: per-(l,a) inverse row-sum and weight ----
    if (tid < LA) {
        float s = 0.0f;
        #pragma unroll
        for (int j = 0; j < C2VAL; ++j) s += s_stats[tid * C2VAL + j];
        s_inv[tid] = (s == 0.0f) ? 1.0f : 1.0f / s;
        s_w[tid]   = layerS[tid / AVAL] * arcS[tid];
    }
    __syncthreads();

    // ---- Phase 2: main elementwise stream ----
    const size_t base = (size_t)n * PER_N;   // 48000 B per n -> 16B aligned
    const float4* T4  = reinterpret_cast<const float4*>(T);
    float4* rt4 = reinterpret_cast<float4*>(out_rt + base);
    float4* tp4 = reinterpret_cast<float4*>(out_tp + base);

    // Division-free index state for i = tid + 256*k (element e = 4*i):
    //   m    = i % 5          (c2 block = 4*m, since e%20 == 4*(i%5))
    //   c    = (i/5) % 20     (i/5 advances by 51|52 -> c += 11|12 mod 20)
    //   la   = i / 100        (i%100 advances by 56 with carry)
    int m    = tid % 5;
    int c    = (tid / 5) % CVAL;
    int la   = tid / 100;
    int r100 = tid % 100;

    #pragma unroll
    for (int k = 0; k < NITER; ++k) {
        const int  i   = tid + k * NTHREADS;
        const bool act = (k < NITER - 1) || (tid < TAIL);  // compile-time split

        float v = 0.0f;
        if (act) {
            const float4 t  = __ldg(&T4[i]);   // L1-resident, coalesced
            const float4 sv = *reinterpret_cast<const float4*>(
                                  s_stats + la * C2VAL + 4 * m);
            const float inv = s_inv[la];
            const float w   = s_w[la];
            float4 r, p;
            r.x = t.x * sv.x * inv;  r.y = t.y * sv.y * inv;
            r.z = t.z * sv.z * inv;  r.w = t.w * sv.w * inv;
            p.x = r.x * w;  p.y = r.y * w;  p.z = r.z * w;  p.w = r.w * w;
            __stcs(&rt4[i], r);   // streaming stores: don't pollute L2
            __stcs(&tp4[i], p);
            v = (p.x + p.y) + (p.z + p.w);
        }

        // Segmented reduction over runs of 5 equal-c lanes (steps d=1,2,4).
        // All 32 lanes execute the shuffles (full mask); inactive lanes carry 0.
        float o;
        o = __shfl_down_sync(0xFFFFFFFFu, v, 1);
        if (m <= 3 && lane < 31) v += o;
        o = __shfl_down_sync(0xFFFFFFFFu, v, 2);
        if (m <= 2 && lane < 30) v += o;
        o = __shfl_down_sync(0xFFFFFFFFu, v, 4);
        if (m == 0 && lane < 28) v += o;

        // Head lanes (segment start, or lane 0 continuing prior warp's segment)
        // have distinct c within this warp-iteration -> non-atomic RMW is safe.
        if (m == 0 || lane == 0)
            s_pqw[warp][c] += v;

        // advance index state
        const bool wrap = (m == 4);
        m = wrap ? 0 : m + 1;
        c += wrap ? 12 : 11;
        if (c >= CVAL) c -= CVAL;
        la += 2; r100 += 56;
        if (r100 >= 100) { la += 1; r100 -= 100; }
    }

    __syncthreads();
    if (tid < CVAL) {
        float s = 0.0f;
        #pragma unroll
        for (int w8 = 0; w8 < NWARPS; ++w8) s += s_pqw[w8][tid];
        out_pq[(size_t)n * CVAL + tid] = s;
    }
}

extern "C" void kernel_launch(void* const* d_in, const int* in_sizes, int n_in,
                              void* d_out, int out_size)
{
    const float* stats  = (const float*)d_in[0];  // [N, L, A, C2]
    const float* layerS = (const float*)d_in[1];  // [L]
    const float* arcS   = (const float*)d_in[2];  // [L, A]
    const float* T      = (const float*)d_in[3];  // [L, A, C, C2]

    const int N = in_sizes[0] / KDIM;

    float* out    = (float*)d_out;
    float* out_pq = out;
    float* out_tp = out_pq + (size_t)N * CVAL;
    float* out_rt = out_tp + (size_t)N * PER_N;

    cgmm_kernel<<<N, NTHREADS>>>(stats, layerS, arcS, T,
                                 out_pq, out_tp, out_rt);
}